// round 12
// baseline (speedup 1.0000x reference)
#include <cuda_runtime.h>
#include <cuda_fp16.h>
#include <cuda_bf16.h>

#define N_NODES_MAX 100352
#define N_EDGES_MAX 1605632
#define FEATS 128
#define NGRAPH 128
#define NCLASS 64
#define SCAN_TILE 4096

// ---------------- scratch (device globals) ----------------------------------
__device__ int    g_deg_out[2][N_NODES_MAX];
__device__ int    g_deg_in[2][N_NODES_MAX];
__device__ int    g_row_ptr[2][N_NODES_MAX];
__device__ int    g_cursor[2][N_NODES_MAX];
__device__ int    g_csr_src[2][N_EDGES_MAX];
__device__ __half g_h[2][(size_t)N_NODES_MAX * FEATS];
__device__ __half g_WT[FEATS * FEATS];           // W^T in fp16: [n][k]
__device__ float  g_hg[2 * NGRAPH * FEATS];
__device__ int    g_cnt[2 * NGRAPH];
// decoupled-lookback scan state
__device__ int                g_tile_counter[2];
__device__ unsigned long long g_tile_state[2][64];   // (flag<<32)|value

// ------- degrees (both branches) + W prep + scan-state reset, one kernel -----
__global__ void degree_prep_kernel(const int* __restrict__ s1, const int* __restrict__ d1, int E1,
                                   const int* __restrict__ s2, const int* __restrict__ d2, int E2,
                                   const float* __restrict__ W, int nb_edges) {
    int blk = blockIdx.x, tid = threadIdx.x;
    if (blk < nb_edges) {
        int e = blk * 256 + tid;
        if (e < E1) {
            atomicAdd(&g_deg_out[0][s1[e]], 1);
            atomicAdd(&g_deg_in[0][d1[e]], 1);
        } else if (e < E1 + E2) {
            int i = e - E1;
            atomicAdd(&g_deg_out[1][s2[i]], 1);
            atomicAdd(&g_deg_in[1][d2[i]], 1);
        }
    } else if (blk < nb_edges + 64) {
        int t = (blk - nb_edges) * 256 + tid;     // 0..16383
        int k = t >> 7, n = t & 127;
        g_WT[n * 128 + k] = __float2half_rn(W[k * 128 + n]);
    } else {
        if (tid < 2)   g_tile_counter[tid] = 0;
        if (tid < 128) g_tile_state[tid >> 6][tid & 63] = 0ull;
    }
}

// -------- decoupled-lookback scan of deg_in -> row_ptr & cursor --------------
__global__ void scan_lookback_kernel(int nnodes) {
    const int br = blockIdx.y;
    __shared__ int s_tile;
    __shared__ int ws[32];
    __shared__ int s_base;

    if (threadIdx.x == 0) s_tile = atomicAdd(&g_tile_counter[br], 1);
    __syncthreads();
    const int blk = s_tile;

    int i = blk * SCAN_TILE + threadIdx.x * 4;
    int lane = threadIdx.x & 31, w = threadIdx.x >> 5;
    int4 v = make_int4(0, 0, 0, 0);
    if (i + 3 < nnodes) v = *(const int4*)&g_deg_in[br][i];
    else {
        if (i     < nnodes) v.x = g_deg_in[br][i];
        if (i + 1 < nnodes) v.y = g_deg_in[br][i + 1];
        if (i + 2 < nnodes) v.z = g_deg_in[br][i + 2];
    }
    int s0 = v.x, s1 = s0 + v.y, s2 = s1 + v.z, s3 = s2 + v.w;
    int x = s3;
#pragma unroll
    for (int o = 1; o < 32; o <<= 1) {
        int y = __shfl_up_sync(0xffffffffu, x, o);
        if (lane >= o) x += y;
    }
    if (lane == 31) ws[w] = x;
    __syncthreads();
    if (w == 0) {
        int t = ws[lane];
#pragma unroll
        for (int o = 1; o < 32; o <<= 1) {
            int y = __shfl_up_sync(0xffffffffu, t, o);
            if (lane >= o) t += y;
        }
        ws[lane] = t;
    }
    __syncthreads();
    const int total = ws[31];

    if (threadIdx.x == 0) {
        volatile unsigned long long* st = g_tile_state[br];
        if (blk == 0) {
            st[0] = (2ull << 32) | (unsigned)total;
            s_base = 0;
        } else {
            st[blk] = (1ull << 32) | (unsigned)total;
            int base = 0;
            int p = blk - 1;
            while (p >= 0) {
                unsigned long long vv;
                do { vv = st[p]; } while ((vv >> 32) == 0ull);
                if ((vv >> 32) == 2ull) { base += (int)(unsigned)vv; break; }
                base += (int)(unsigned)vv;
                p--;
            }
            st[blk] = (2ull << 32) | (unsigned)(base + total);
            s_base = base;
        }
    }
    __syncthreads();

    int base = s_base + (w ? ws[w - 1] : 0) + (x - s3);
    int4 e = make_int4(base, base + s0, base + s1, base + s2);
    if (i + 3 < nnodes) {
        *(int4*)&g_row_ptr[br][i] = e;
        *(int4*)&g_cursor[br][i]  = e;
    } else {
        if (i     < nnodes) { g_row_ptr[br][i]     = e.x; g_cursor[br][i]     = e.x; }
        if (i + 1 < nnodes) { g_row_ptr[br][i + 1] = e.y; g_cursor[br][i + 1] = e.y; }
        if (i + 2 < nnodes) { g_row_ptr[br][i + 2] = e.z; g_cursor[br][i + 2] = e.z; }
    }
}

// ---------------- CSR fill, both branches ------------------------------------
__global__ void fill2_kernel(const int* __restrict__ s1, const int* __restrict__ d1, int E1,
                             const int* __restrict__ s2, const int* __restrict__ d2, int E2) {
    int e = blockIdx.x * blockDim.x + threadIdx.x;
    if (e < E1) {
        int pos = atomicAdd(&g_cursor[0][d1[e]], 1);
        g_csr_src[0][pos] = s1[e];
    } else if (e < E1 + E2) {
        int i = e - E1;
        int pos = atomicAdd(&g_cursor[1][d2[i]], 1);
        g_csr_src[1][pos] = s2[i];
    }
}

// ---------------- fp16 MMA / ldmatrix helpers --------------------------------
__device__ __forceinline__ void mma_f16(float4& c,
                                        unsigned a0, unsigned a1,
                                        unsigned a2, unsigned a3,
                                        unsigned b0, unsigned b1) {
    asm volatile(
        "mma.sync.aligned.m16n8k16.row.col.f32.f16.f16.f32 "
        "{%0,%1,%2,%3}, {%4,%5,%6,%7}, {%8,%9}, {%0,%1,%2,%3};\n"
        : "+f"(c.x), "+f"(c.y), "+f"(c.z), "+f"(c.w)
        : "r"(a0), "r"(a1), "r"(a2), "r"(a3), "r"(b0), "r"(b1));
}

__device__ __forceinline__ void ldsm_x4(unsigned& r0, unsigned& r1,
                                        unsigned& r2, unsigned& r3, unsigned addr) {
    asm volatile("ldmatrix.sync.aligned.m8n8.x4.shared.b16 {%0,%1,%2,%3}, [%4];"
                 : "=r"(r0), "=r"(r1), "=r"(r2), "=r"(r3) : "r"(addr));
}
__device__ __forceinline__ void ldsm_x2(unsigned& r0, unsigned& r1, unsigned addr) {
    asm volatile("ldmatrix.sync.aligned.m8n8.x2.shared.b16 {%0,%1}, [%2];"
                 : "=r"(r0), "=r"(r1) : "r"(addr));
}

// ---------------- GEMM (fp16 HMMA + ldmatrix): g_h[br] = ds * (feat @ W) -----
// block 256 (8 warps as 4m x 2n), tile 64x128, K=128; warp tile m16 x n64
// 52 KB smem -> 3 CTAs/SM with launch_bounds(256,3)
#define AS 136  // half stride per smem row (272B, 16B-multiple -> ldmatrix ok)
__global__ void __launch_bounds__(256, 3)
gemm_fp16_kernel(const float* __restrict__ feat0, const float* __restrict__ feat1,
                 int nnodes) {
    extern __shared__ __half sm[];
    __half* sA  = sm;              // [64][AS]   feat tile (fp16), row-major
    __half* sBt = sm + 64 * AS;    // [128][AS]  W^T: [n][k]

    const int br   = blockIdx.y;
    const float* feat = br ? feat1 : feat0;
    const int tid  = threadIdx.x;
    const int row0 = blockIdx.x * 64;
    const float4* F4  = (const float4*)feat;
    const uint4*  WT4 = (const uint4*)g_WT;

    // load B: 128 rows x 16 uint4 per row = 2048 uint4, 8 per thread
#pragma unroll
    for (int i = 0; i < 8; i++) {
        int idx = tid + i * 256;
        int r = idx >> 4, c = idx & 15;
        *(uint4*)&sBt[r * AS + c * 8] = WT4[idx];
    }
    // load A: 64 rows x 16 uint4-slots = 1024, 4 per thread (2 float4 -> 1 uint4)
#pragma unroll
    for (int i = 0; i < 4; i++) {
        int idx = tid + i * 256;
        int r = idx >> 4, c = idx & 15;
        float4 f0 = make_float4(0.f, 0.f, 0.f, 0.f), f1 = f0;
        if (row0 + r < nnodes) {
            f0 = F4[(size_t)(row0 + r) * 32 + 2 * c];
            f1 = F4[(size_t)(row0 + r) * 32 + 2 * c + 1];
        }
        union { __half2 h[4]; uint4 u; } p;
        p.h[0] = __floats2half2_rn(f0.x, f0.y);
        p.h[1] = __floats2half2_rn(f0.z, f0.w);
        p.h[2] = __floats2half2_rn(f1.x, f1.y);
        p.h[3] = __floats2half2_rn(f1.z, f1.w);
        *(uint4*)&sA[r * AS + c * 8] = p.u;
    }
    __syncthreads();

    const int w = tid >> 5, lane = tid & 31;
    const int wm = w & 3;                  // 0..3 -> m
    const int wn = w >> 2;                 // 0..1 -> n
    const int r0 = wm * 16;
    const int n0 = wn * 64;
    const int gid8 = lane >> 2, tig = lane & 3;

    unsigned aAddr = (unsigned)__cvta_generic_to_shared(
        &sA[(r0 + (lane & 15)) * AS + (lane >> 4) * 8]);
    int bl = lane & 15;
    unsigned bAddr = (unsigned)__cvta_generic_to_shared(
        &sBt[(n0 + (bl & 7)) * AS + (bl >> 3) * 8]);

    float4 c[8];
#pragma unroll
    for (int j = 0; j < 8; j++) c[j] = make_float4(0.f, 0.f, 0.f, 0.f);

#pragma unroll
    for (int kk = 0; kk < 8; kk++) {
        unsigned koff = kk * 32;           // 16 halves = 32 bytes
        unsigned a0, a1, a2, a3;
        ldsm_x4(a0, a1, a2, a3, aAddr + koff);
#pragma unroll
        for (int j = 0; j < 8; j++) {
            unsigned b0, b1;
            ldsm_x2(b0, b1, bAddr + j * (8 * AS * 2) + koff);
            mma_f16(c[j], a0, a1, a2, a3, b0, b1);
        }
    }

    unsigned* H = (unsigned*)g_h[br];
    int ra = row0 + r0 + gid8;
    int rb = ra + 8;
    bool va = ra < nnodes, vb = rb < nnodes;
    float dsa = 0.f, dsb = 0.f;
    if (va) { int d = g_deg_out[br][ra]; dsa = rsqrtf((float)(d > 1 ? d : 1)); }
    if (vb) { int d = g_deg_out[br][rb]; dsb = rsqrtf((float)(d > 1 ? d : 1)); }
#pragma unroll
    for (int j = 0; j < 8; j++) {
        int colw = (n0 + j * 8 + 2 * tig) >> 1;  // half2 index (64 per row)
        if (va) {
            __half2 o = __floats2half2_rn(c[j].x * dsa, c[j].y * dsa);
            H[(size_t)ra * 64 + colw] = *(unsigned*)&o;
        }
        if (vb) {
            __half2 o = __floats2half2_rn(c[j].z * dsb, c[j].w * dsb);
            H[(size_t)rb * 64 + colw] = *(unsigned*)&o;
        }
    }
}

// ---------------- gather-aggregate + fused epilogue (warp per node) ----------
__global__ void gather2_kernel(const int* __restrict__ gid0,
                               const int* __restrict__ gid1,
                               const float* __restrict__ bvec, int nnodes) {
    int t = blockIdx.x * blockDim.x + threadIdx.x;
    int n2 = t >> 5;
    if (n2 >= 2 * nnodes) return;
    int br = (n2 >= nnodes) ? 1 : 0;
    int n = n2 - br * nnodes;
    int lane = t & 31;

    int beg = __ldg(&g_row_ptr[br][n]);
    int dg  = __ldg(&g_deg_in[br][n]);
    int end = beg + dg;
    const uint2* H2 = (const uint2*)g_h[br];   // 8B per lane = 4 halves
    const int* csr = g_csr_src[br];

    float4 acc = make_float4(0.f, 0.f, 0.f, 0.f);

#define ACCU(u) { float2 f_; \
    f_ = __half22float2(*(__half2*)&(u).x); acc.x += f_.x; acc.y += f_.y; \
    f_ = __half22float2(*(__half2*)&(u).y); acc.z += f_.x; acc.w += f_.y; }

    int e = beg;
    for (; e + 8 <= end; e += 8) {
        int s0 = __ldg(csr + e);
        int s1 = __ldg(csr + e + 1);
        int s2 = __ldg(csr + e + 2);
        int s3 = __ldg(csr + e + 3);
        int s4 = __ldg(csr + e + 4);
        int s5 = __ldg(csr + e + 5);
        int s6 = __ldg(csr + e + 6);
        int s7 = __ldg(csr + e + 7);
        uint2 u0 = H2[(size_t)s0 * 32 + lane];
        uint2 u1 = H2[(size_t)s1 * 32 + lane];
        uint2 u2 = H2[(size_t)s2 * 32 + lane];
        uint2 u3 = H2[(size_t)s3 * 32 + lane];
        uint2 u4 = H2[(size_t)s4 * 32 + lane];
        uint2 u5 = H2[(size_t)s5 * 32 + lane];
        uint2 u6 = H2[(size_t)s6 * 32 + lane];
        uint2 u7 = H2[(size_t)s7 * 32 + lane];
        ACCU(u0); ACCU(u1); ACCU(u2); ACCU(u3);
        ACCU(u4); ACCU(u5); ACCU(u6); ACCU(u7);
    }
    for (; e + 2 <= end; e += 2) {
        int s0 = __ldg(csr + e);
        int s1 = __ldg(csr + e + 1);
        uint2 u0 = H2[(size_t)s0 * 32 + lane];
        uint2 u1 = H2[(size_t)s1 * 32 + lane];
        ACCU(u0); ACCU(u1);
    }
    if (e < end) {
        int s = __ldg(csr + e);
        uint2 u = H2[(size_t)s * 32 + lane];
        ACCU(u);
    }
#undef ACCU

    float din = rsqrtf((float)(dg > 1 ? dg : 1));
    float4 bb = __ldg((const float4*)bvec + lane);
    float4 v = make_float4(acc.x * din + bb.x, acc.y * din + bb.y,
                           acc.z * din + bb.z, acc.w * din + bb.w);
    float ss = v.x * v.x + v.y * v.y + v.z * v.z + v.w * v.w;
#pragma unroll
    for (int o = 16; o; o >>= 1) ss += __shfl_xor_sync(0xffffffffu, ss, o);
    float inv = 1.f / fmaxf(sqrtf(ss), 1e-12f);

    v.x = 1.f / (1.f + __expf(-v.x * inv));
    v.y = 1.f / (1.f + __expf(-v.y * inv));
    v.z = 1.f / (1.f + __expf(-v.z * inv));
    v.w = 1.f / (1.f + __expf(-v.w * inv));

    const int* gid = br ? gid1 : gid0;
    int g = __ldg(gid + n);
    atomicAdd((float4*)g_hg + (size_t)(br * NGRAPH + g) * 32 + lane, v);
    if (lane == 0) atomicAdd(&g_cnt[br * NGRAPH + g], 1);
}

// ---------------- classifier + pairwise distance (block per graph) -----------
__global__ void final_kernel(const float* __restrict__ Wc,
                             const float* __restrict__ bc,
                             float* __restrict__ out) {
    int g = blockIdx.x, tid = threadIdx.x;  // 64 threads
    __shared__ float s1[128], s2[128];
    __shared__ float part[2];

    float c1 = fmaxf((float)g_cnt[g], 1.f);
    float c2 = fmaxf((float)g_cnt[NGRAPH + g], 1.f);
    for (int i = tid; i < 128; i += 64) {
        s1[i] = g_hg[g * 128 + i] / c1;
        s2[i] = g_hg[NGRAPH * 128 + g * 128 + i] / c2;
    }
    __syncthreads();

    float l1 = bc[tid], l2 = l1;
#pragma unroll 4
    for (int k = 0; k < 128; k++) {
        float w = Wc[k * NCLASS + tid];
        l1 += s1[k] * w;
        l2 += s2[k] * w;
    }
    float dd = l1 - l2 + 1e-6f;
    float sq = dd * dd;
#pragma unroll
    for (int o = 16; o; o >>= 1) sq += __shfl_xor_sync(0xffffffffu, sq, o);
    if ((tid & 31) == 0) part[tid >> 5] = sq;
    __syncthreads();
    if (tid == 0) out[g] = sqrtf(part[0] + part[1]);
}

// ---------------- launch ------------------------------------------------------
extern "C" void kernel_launch(void* const* d_in, const int* in_sizes, int n_in,
                              void* d_out, int out_size) {
    const float* feat1 = (const float*)d_in[0];
    const float* feat2 = (const float*)d_in[1];
    const int* src1 = (const int*)d_in[2];
    const int* dst1 = (const int*)d_in[3];
    const int* gid1 = (const int*)d_in[4];
    const int* src2 = (const int*)d_in[5];
    const int* dst2 = (const int*)d_in[6];
    const int* gid2 = (const int*)d_in[7];
    const float* W  = (const float*)d_in[8];
    const float* b  = (const float*)d_in[9];
    const float* Wc = (const float*)d_in[10];
    const float* bc = (const float*)d_in[11];

    const int NN = in_sizes[0] / FEATS;
    const int E1 = in_sizes[2], E2 = in_sizes[5];
    const int nblk = (NN + SCAN_TILE - 1) / SCAN_TILE;

    void *p_deg_out, *p_deg_in, *p_hg, *p_cnt;
    cudaGetSymbolAddress(&p_deg_out, g_deg_out);
    cudaGetSymbolAddress(&p_deg_in,  g_deg_in);
    cudaGetSymbolAddress(&p_hg,      g_hg);
    cudaGetSymbolAddress(&p_cnt,     g_cnt);

    const int SMEM = (64 + 128) * AS * (int)sizeof(__half);  // 52224
    cudaFuncSetAttribute(gemm_fp16_kernel,
                         cudaFuncAttributeMaxDynamicSharedMemorySize, SMEM);

    cudaMemsetAsync(p_hg, 0, 2 * NGRAPH * FEATS * sizeof(float));
    cudaMemsetAsync(p_cnt, 0, 2 * NGRAPH * sizeof(int));
    cudaMemsetAsync(p_deg_out, 0, 2 * N_NODES_MAX * sizeof(int));
    cudaMemsetAsync(p_deg_in,  0, 2 * N_NODES_MAX * sizeof(int));

    const int nb_edges = (E1 + E2 + 255) / 256;
    degree_prep_kernel<<<nb_edges + 65, 256>>>(src1, dst1, E1, src2, dst2, E2, W, nb_edges);

    {
        dim3 grid(nblk, 2);
        scan_lookback_kernel<<<grid, 1024>>>(NN);
    }
    fill2_kernel<<<(E1 + E2 + 255) / 256, 256>>>(src1, dst1, E1, src2, dst2, E2);

    {
        dim3 grid((NN + 63) / 64, 2);
        gemm_fp16_kernel<<<grid, 256, SMEM>>>(feat1, feat2, NN);
    }
    {
        long long threads = (long long)2 * NN * 32;
        int blocks = (int)((threads + 255) / 256);
        gather2_kernel<<<blocks, 256>>>(gid1, gid2, b, NN);
    }
    final_kernel<<<NGRAPH, 64>>>(Wc, bc, (float*)d_out);
}

// round 13
// speedup vs baseline: 1.2527x; 1.2527x over previous
#include <cuda_runtime.h>
#include <cuda_fp16.h>
#include <cuda_bf16.h>

#define N_NODES_MAX 100352
#define N_EDGES_MAX 1605632
#define FEATS 128
#define NGRAPH 128
#define NCLASS 64
#define SCAN_TILE 4096

// ---------------- scratch (device globals) ----------------------------------
__device__ int    g_deg_out[2][N_NODES_MAX];
__device__ int    g_deg_in[2][N_NODES_MAX];
__device__ int    g_row_ptr[2][N_NODES_MAX];
__device__ int    g_cursor[2][N_NODES_MAX];
__device__ int    g_csr_src[2][N_EDGES_MAX];
__device__ __half g_h[2][(size_t)N_NODES_MAX * FEATS];
__device__ __half g_WT[FEATS * FEATS];           // W^T in fp16: [n][k]
__device__ float  g_hg[2 * NGRAPH * FEATS];
__device__ int    g_cnt[2 * NGRAPH];
// decoupled-lookback scan state
__device__ int                g_tile_counter[2];
__device__ unsigned long long g_tile_state[2][64];   // (flag<<32)|value

// ------- degrees (both branches) + W prep + scan-state reset, one kernel -----
__global__ void degree_prep_kernel(const int* __restrict__ s1, const int* __restrict__ d1, int E1,
                                   const int* __restrict__ s2, const int* __restrict__ d2, int E2,
                                   const float* __restrict__ W, int nb_edges) {
    int blk = blockIdx.x, tid = threadIdx.x;
    if (blk < nb_edges) {
        int e = blk * 256 + tid;
        if (e < E1) {
            atomicAdd(&g_deg_out[0][s1[e]], 1);
            atomicAdd(&g_deg_in[0][d1[e]], 1);
        } else if (e < E1 + E2) {
            int i = e - E1;
            atomicAdd(&g_deg_out[1][s2[i]], 1);
            atomicAdd(&g_deg_in[1][d2[i]], 1);
        }
    } else if (blk < nb_edges + 64) {
        int t = (blk - nb_edges) * 256 + tid;     // 0..16383
        int k = t >> 7, n = t & 127;
        g_WT[n * 128 + k] = __float2half_rn(W[k * 128 + n]);
    } else {
        if (tid < 2)   g_tile_counter[tid] = 0;
        if (tid < 128) g_tile_state[tid >> 6][tid & 63] = 0ull;
    }
}

// -------- decoupled-lookback scan of deg_in -> row_ptr & cursor --------------
__global__ void scan_lookback_kernel(int nnodes) {
    const int br = blockIdx.y;
    __shared__ int s_tile;
    __shared__ int ws[32];
    __shared__ int s_base;

    if (threadIdx.x == 0) s_tile = atomicAdd(&g_tile_counter[br], 1);
    __syncthreads();
    const int blk = s_tile;

    int i = blk * SCAN_TILE + threadIdx.x * 4;
    int lane = threadIdx.x & 31, w = threadIdx.x >> 5;
    int4 v = make_int4(0, 0, 0, 0);
    if (i + 3 < nnodes) v = *(const int4*)&g_deg_in[br][i];
    else {
        if (i     < nnodes) v.x = g_deg_in[br][i];
        if (i + 1 < nnodes) v.y = g_deg_in[br][i + 1];
        if (i + 2 < nnodes) v.z = g_deg_in[br][i + 2];
    }
    int s0 = v.x, s1 = s0 + v.y, s2 = s1 + v.z, s3 = s2 + v.w;
    int x = s3;
#pragma unroll
    for (int o = 1; o < 32; o <<= 1) {
        int y = __shfl_up_sync(0xffffffffu, x, o);
        if (lane >= o) x += y;
    }
    if (lane == 31) ws[w] = x;
    __syncthreads();
    if (w == 0) {
        int t = ws[lane];
#pragma unroll
        for (int o = 1; o < 32; o <<= 1) {
            int y = __shfl_up_sync(0xffffffffu, t, o);
            if (lane >= o) t += y;
        }
        ws[lane] = t;
    }
    __syncthreads();
    const int total = ws[31];

    if (threadIdx.x == 0) {
        volatile unsigned long long* st = g_tile_state[br];
        if (blk == 0) {
            st[0] = (2ull << 32) | (unsigned)total;
            s_base = 0;
        } else {
            st[blk] = (1ull << 32) | (unsigned)total;
            int base = 0;
            int p = blk - 1;
            while (p >= 0) {
                unsigned long long vv;
                do { vv = st[p]; } while ((vv >> 32) == 0ull);
                if ((vv >> 32) == 2ull) { base += (int)(unsigned)vv; break; }
                base += (int)(unsigned)vv;
                p--;
            }
            st[blk] = (2ull << 32) | (unsigned)(base + total);
            s_base = base;
        }
    }
    __syncthreads();

    int base = s_base + (w ? ws[w - 1] : 0) + (x - s3);
    int4 e = make_int4(base, base + s0, base + s1, base + s2);
    if (i + 3 < nnodes) {
        *(int4*)&g_row_ptr[br][i] = e;
        *(int4*)&g_cursor[br][i]  = e;
    } else {
        if (i     < nnodes) { g_row_ptr[br][i]     = e.x; g_cursor[br][i]     = e.x; }
        if (i + 1 < nnodes) { g_row_ptr[br][i + 1] = e.y; g_cursor[br][i + 1] = e.y; }
        if (i + 2 < nnodes) { g_row_ptr[br][i + 2] = e.z; g_cursor[br][i + 2] = e.z; }
    }
}

// ---------------- fp16 MMA / ldmatrix helpers --------------------------------
__device__ __forceinline__ void mma_f16(float4& c,
                                        unsigned a0, unsigned a1,
                                        unsigned a2, unsigned a3,
                                        unsigned b0, unsigned b1) {
    asm volatile(
        "mma.sync.aligned.m16n8k16.row.col.f32.f16.f16.f32 "
        "{%0,%1,%2,%3}, {%4,%5,%6,%7}, {%8,%9}, {%0,%1,%2,%3};\n"
        : "+f"(c.x), "+f"(c.y), "+f"(c.z), "+f"(c.w)
        : "r"(a0), "r"(a1), "r"(a2), "r"(a3), "r"(b0), "r"(b1));
}

__device__ __forceinline__ void ldsm_x4(unsigned& r0, unsigned& r1,
                                        unsigned& r2, unsigned& r3, unsigned addr) {
    asm volatile("ldmatrix.sync.aligned.m8n8.x4.shared.b16 {%0,%1,%2,%3}, [%4];"
                 : "=r"(r0), "=r"(r1), "=r"(r2), "=r"(r3) : "r"(addr));
}
__device__ __forceinline__ void ldsm_x2(unsigned& r0, unsigned& r1, unsigned addr) {
    asm volatile("ldmatrix.sync.aligned.m8n8.x2.shared.b16 {%0,%1}, [%2];"
                 : "=r"(r0), "=r"(r1) : "r"(addr));
}

// ----- FUSED kernel: GEMM tiles + interleaved CSR-fill workers ---------------
// blk%4==3 -> fill worker (grid-stride over all edges); else R10 GEMM tile.
// GEMM: block 256 (8 warps as 4x2), tile 128x128, K=128; warp tile m32 x n64
#define AS 136  // half stride per smem row (272B, 16B-multiple -> ldmatrix ok)
__global__ void __launch_bounds__(256, 2)
fillgemm_kernel(const float* __restrict__ feat0, const float* __restrict__ feat1,
                const int* __restrict__ s1, const int* __restrict__ d1, int E1,
                const int* __restrict__ s2, const int* __restrict__ d2, int E2,
                int ngx, int nnodes) {
    const int blk = blockIdx.x;
    const int tid = threadIdx.x;

    if ((blk & 3) == 3) {
        // ---------------- fill role ----------------
        int fid = blk >> 2;
        int nfill = gridDim.x >> 2;
        int stride = nfill * 256;
        for (int e = fid * 256 + tid; e < E1 + E2; e += stride) {
            if (e < E1) {
                int pos = atomicAdd(&g_cursor[0][d1[e]], 1);
                g_csr_src[0][pos] = s1[e];
            } else {
                int i = e - E1;
                int pos = atomicAdd(&g_cursor[1][d2[i]], 1);
                g_csr_src[1][pos] = s2[i];
            }
        }
        return;
    }

    // ---------------- GEMM role (verbatim R10 core) ----------------
    int gid_ = blk - (blk >> 2);
    if (gid_ >= 2 * ngx) return;
    const int br = (gid_ >= ngx) ? 1 : 0;
    const int row0 = (gid_ - br * ngx) * 128;

    extern __shared__ __half sm[];
    __half* sA  = sm;              // [128][AS]  feat tile (fp16), row-major
    __half* sBt = sm + 128 * AS;   // [128][AS]  W^T: [n][k]

    const float* feat = br ? feat1 : feat0;
    const float4* F4  = (const float4*)feat;
    const uint4*  WT4 = (const uint4*)g_WT;

#pragma unroll
    for (int i = 0; i < 8; i++) {
        int idx = tid + i * 256;          // 2048 uint4 total
        int r = idx >> 4, c = idx & 15;   // row, uint4-col (8 halves)
        float4 f0 = make_float4(0.f, 0.f, 0.f, 0.f), f1 = f0;
        if (row0 + r < nnodes) {
            f0 = F4[(size_t)(row0 + r) * 32 + 2 * c];
            f1 = F4[(size_t)(row0 + r) * 32 + 2 * c + 1];
        }
        union { __half2 h[4]; uint4 u; } p;
        p.h[0] = __floats2half2_rn(f0.x, f0.y);
        p.h[1] = __floats2half2_rn(f0.z, f0.w);
        p.h[2] = __floats2half2_rn(f1.x, f1.y);
        p.h[3] = __floats2half2_rn(f1.z, f1.w);
        *(uint4*)&sA[r * AS + c * 8] = p.u;
        *(uint4*)&sBt[r * AS + c * 8] = WT4[idx];
    }
    __syncthreads();

    const int w = tid >> 5, lane = tid & 31;
    const int wm = w & 3;
    const int warp_n = w >> 2;             // 0..1
    const int r0 = wm * 32;
    const int n0 = warp_n * 64;
    const int gid8 = lane >> 2, tig = lane & 3;

    unsigned aAddr0 = (unsigned)__cvta_generic_to_shared(
        &sA[(r0 + (lane & 15)) * AS + (lane >> 4) * 8]);
    unsigned aAddr1 = (unsigned)__cvta_generic_to_shared(
        &sA[(r0 + 16 + (lane & 15)) * AS + (lane >> 4) * 8]);
    int bl = lane & 15;
    unsigned bAddr = (unsigned)__cvta_generic_to_shared(
        &sBt[(n0 + (bl & 7)) * AS + (bl >> 3) * 8]);

    float4 c[2][8];
#pragma unroll
    for (int m = 0; m < 2; m++)
#pragma unroll
        for (int j = 0; j < 8; j++) c[m][j] = make_float4(0.f, 0.f, 0.f, 0.f);

#pragma unroll
    for (int kk = 0; kk < 8; kk++) {
        unsigned koff = kk * 32;           // 16 halves = 32 bytes
        unsigned a[2][4];
        ldsm_x4(a[0][0], a[0][1], a[0][2], a[0][3], aAddr0 + koff);
        ldsm_x4(a[1][0], a[1][1], a[1][2], a[1][3], aAddr1 + koff);
        unsigned b[8][2];
#pragma unroll
        for (int j = 0; j < 8; j++)
            ldsm_x2(b[j][0], b[j][1], bAddr + j * (8 * AS * 2) + koff);
#pragma unroll
        for (int m = 0; m < 2; m++)
#pragma unroll
            for (int j = 0; j < 8; j++)
                mma_f16(c[m][j], a[m][0], a[m][1], a[m][2], a[m][3],
                        b[j][0], b[j][1]);
    }

    unsigned* H = (unsigned*)g_h[br];
#pragma unroll
    for (int m = 0; m < 2; m++) {
        int ra = row0 + r0 + m * 16 + gid8;
        int rb = ra + 8;
        bool va = ra < nnodes, vb = rb < nnodes;
        float dsa = 0.f, dsb = 0.f;
        if (va) { int d = g_deg_out[br][ra]; dsa = rsqrtf((float)(d > 1 ? d : 1)); }
        if (vb) { int d = g_deg_out[br][rb]; dsb = rsqrtf((float)(d > 1 ? d : 1)); }
#pragma unroll
        for (int j = 0; j < 8; j++) {
            int colw = (n0 + j * 8 + 2 * tig) >> 1;  // half2 index (64 per row)
            if (va) {
                __half2 o = __floats2half2_rn(c[m][j].x * dsa, c[m][j].y * dsa);
                H[(size_t)ra * 64 + colw] = *(unsigned*)&o;
            }
            if (vb) {
                __half2 o = __floats2half2_rn(c[m][j].z * dsb, c[m][j].w * dsb);
                H[(size_t)rb * 64 + colw] = *(unsigned*)&o;
            }
        }
    }
}

// ---------------- gather-aggregate + fused epilogue (warp per node) ----------
__global__ void gather2_kernel(const int* __restrict__ gid0,
                               const int* __restrict__ gid1,
                               const float* __restrict__ bvec, int nnodes) {
    int t = blockIdx.x * blockDim.x + threadIdx.x;
    int n2 = t >> 5;
    if (n2 >= 2 * nnodes) return;
    int br = (n2 >= nnodes) ? 1 : 0;
    int n = n2 - br * nnodes;
    int lane = t & 31;

    int beg = __ldg(&g_row_ptr[br][n]);
    int dg  = __ldg(&g_deg_in[br][n]);
    int end = beg + dg;
    const uint2* H2 = (const uint2*)g_h[br];   // 8B per lane = 4 halves
    const int* csr = g_csr_src[br];

    float4 acc = make_float4(0.f, 0.f, 0.f, 0.f);

#define ACCU(u) { float2 f_; \
    f_ = __half22float2(*(__half2*)&(u).x); acc.x += f_.x; acc.y += f_.y; \
    f_ = __half22float2(*(__half2*)&(u).y); acc.z += f_.x; acc.w += f_.y; }

    int e = beg;
    for (; e + 8 <= end; e += 8) {
        int s0 = __ldg(csr + e);
        int s1 = __ldg(csr + e + 1);
        int s2 = __ldg(csr + e + 2);
        int s3 = __ldg(csr + e + 3);
        int s4 = __ldg(csr + e + 4);
        int s5 = __ldg(csr + e + 5);
        int s6 = __ldg(csr + e + 6);
        int s7 = __ldg(csr + e + 7);
        uint2 u0 = H2[(size_t)s0 * 32 + lane];
        uint2 u1 = H2[(size_t)s1 * 32 + lane];
        uint2 u2 = H2[(size_t)s2 * 32 + lane];
        uint2 u3 = H2[(size_t)s3 * 32 + lane];
        uint2 u4 = H2[(size_t)s4 * 32 + lane];
        uint2 u5 = H2[(size_t)s5 * 32 + lane];
        uint2 u6 = H2[(size_t)s6 * 32 + lane];
        uint2 u7 = H2[(size_t)s7 * 32 + lane];
        ACCU(u0); ACCU(u1); ACCU(u2); ACCU(u3);
        ACCU(u4); ACCU(u5); ACCU(u6); ACCU(u7);
    }
    for (; e + 2 <= end; e += 2) {
        int s0 = __ldg(csr + e);
        int s1 = __ldg(csr + e + 1);
        uint2 u0 = H2[(size_t)s0 * 32 + lane];
        uint2 u1 = H2[(size_t)s1 * 32 + lane];
        ACCU(u0); ACCU(u1);
    }
    if (e < end) {
        int s = __ldg(csr + e);
        uint2 u = H2[(size_t)s * 32 + lane];
        ACCU(u);
    }
#undef ACCU

    float din = rsqrtf((float)(dg > 1 ? dg : 1));
    float4 bb = __ldg((const float4*)bvec + lane);
    float4 v = make_float4(acc.x * din + bb.x, acc.y * din + bb.y,
                           acc.z * din + bb.z, acc.w * din + bb.w);
    float ss = v.x * v.x + v.y * v.y + v.z * v.z + v.w * v.w;
#pragma unroll
    for (int o = 16; o; o >>= 1) ss += __shfl_xor_sync(0xffffffffu, ss, o);
    float inv = 1.f / fmaxf(sqrtf(ss), 1e-12f);

    v.x = 1.f / (1.f + __expf(-v.x * inv));
    v.y = 1.f / (1.f + __expf(-v.y * inv));
    v.z = 1.f / (1.f + __expf(-v.z * inv));
    v.w = 1.f / (1.f + __expf(-v.w * inv));

    const int* gid = br ? gid1 : gid0;
    int g = __ldg(gid + n);
    atomicAdd((float4*)g_hg + (size_t)(br * NGRAPH + g) * 32 + lane, v);
    if (lane == 0) atomicAdd(&g_cnt[br * NGRAPH + g], 1);
}

// ---------------- classifier + pairwise distance (block per graph) -----------
__global__ void final_kernel(const float* __restrict__ Wc,
                             const float* __restrict__ bc,
                             float* __restrict__ out) {
    int g = blockIdx.x, tid = threadIdx.x;  // 64 threads
    __shared__ float s1[128], s2[128];
    __shared__ float part[2];

    float c1 = fmaxf((float)g_cnt[g], 1.f);
    float c2 = fmaxf((float)g_cnt[NGRAPH + g], 1.f);
    for (int i = tid; i < 128; i += 64) {
        s1[i] = g_hg[g * 128 + i] / c1;
        s2[i] = g_hg[NGRAPH * 128 + g * 128 + i] / c2;
    }
    __syncthreads();

    float l1 = bc[tid], l2 = l1;
#pragma unroll 4
    for (int k = 0; k < 128; k++) {
        float w = Wc[k * NCLASS + tid];
        l1 += s1[k] * w;
        l2 += s2[k] * w;
    }
    float dd = l1 - l2 + 1e-6f;
    float sq = dd * dd;
#pragma unroll
    for (int o = 16; o; o >>= 1) sq += __shfl_xor_sync(0xffffffffu, sq, o);
    if ((tid & 31) == 0) part[tid >> 5] = sq;
    __syncthreads();
    if (tid == 0) out[g] = sqrtf(part[0] + part[1]);
}

// ---------------- launch ------------------------------------------------------
extern "C" void kernel_launch(void* const* d_in, const int* in_sizes, int n_in,
                              void* d_out, int out_size) {
    const float* feat1 = (const float*)d_in[0];
    const float* feat2 = (const float*)d_in[1];
    const int* src1 = (const int*)d_in[2];
    const int* dst1 = (const int*)d_in[3];
    const int* gid1 = (const int*)d_in[4];
    const int* src2 = (const int*)d_in[5];
    const int* dst2 = (const int*)d_in[6];
    const int* gid2 = (const int*)d_in[7];
    const float* W  = (const float*)d_in[8];
    const float* b  = (const float*)d_in[9];
    const float* Wc = (const float*)d_in[10];
    const float* bc = (const float*)d_in[11];

    const int NN = in_sizes[0] / FEATS;
    const int E1 = in_sizes[2], E2 = in_sizes[5];
    const int nblk = (NN + SCAN_TILE - 1) / SCAN_TILE;

    void *p_deg_out, *p_deg_in, *p_hg, *p_cnt;
    cudaGetSymbolAddress(&p_deg_out, g_deg_out);
    cudaGetSymbolAddress(&p_deg_in,  g_deg_in);
    cudaGetSymbolAddress(&p_hg,      g_hg);
    cudaGetSymbolAddress(&p_cnt,     g_cnt);

    const int SMEM = 2 * 128 * AS * (int)sizeof(__half);  // 69632
    cudaFuncSetAttribute(fillgemm_kernel,
                         cudaFuncAttributeMaxDynamicSharedMemorySize, SMEM);

    cudaMemsetAsync(p_hg, 0, 2 * NGRAPH * FEATS * sizeof(float));
    cudaMemsetAsync(p_cnt, 0, 2 * NGRAPH * sizeof(int));
    cudaMemsetAsync(p_deg_out, 0, 2 * N_NODES_MAX * sizeof(int));
    cudaMemsetAsync(p_deg_in,  0, 2 * N_NODES_MAX * sizeof(int));

    const int nb_edges = (E1 + E2 + 255) / 256;
    degree_prep_kernel<<<nb_edges + 65, 256>>>(src1, dst1, E1, src2, dst2, E2, W, nb_edges);

    {
        dim3 grid(nblk, 2);
        scan_lookback_kernel<<<grid, 1024>>>(NN);
    }

    {
        const int ngx = (NN + 127) / 128;
        const int NBG = 2 * ngx;
        const int T = (NBG * 4 + 2) / 3;   // every 4th block is a fill worker
        fillgemm_kernel<<<T, 256, SMEM>>>(feat1, feat2,
                                          src1, dst1, E1, src2, dst2, E2,
                                          ngx, NN);
    }
    {
        long long threads = (long long)2 * NN * 32;
        int blocks = (int)((threads + 255) / 256);
        gather2_kernel<<<blocks, 256>>>(gid1, gid2, b, NN);
    }
    final_kernel<<<NGRAPH, 64>>>(Wc, bc, (float*)d_out);
}

// round 14
// speedup vs baseline: 1.2938x; 1.0328x over previous
#include <cuda_runtime.h>
#include <cuda_fp16.h>
#include <cuda_bf16.h>

#define N_NODES_MAX 100352
#define N_EDGES_MAX 1605632
#define FEATS 128
#define NGRAPH 128
#define NCLASS 64
#define SCAN_TILE 4096

// ---------------- scratch (device globals) ----------------------------------
__device__ int    g_deg_out[2][N_NODES_MAX];
__device__ int    g_deg_in[2][N_NODES_MAX];
__device__ int    g_row_ptr[2][N_NODES_MAX];
__device__ int    g_cursor[2][N_NODES_MAX];
__device__ int    g_csr_src[2][N_EDGES_MAX];
__device__ __half g_h[2][(size_t)N_NODES_MAX * FEATS];
__device__ __half g_WT[FEATS * FEATS];           // W^T in fp16: [n][k]
__device__ float  g_hg[2 * NGRAPH * FEATS];
__device__ int    g_cnt[2 * NGRAPH];
// decoupled-lookback scan state
__device__ int                g_tile_counter[2];
__device__ unsigned long long g_tile_state[2][64];   // (flag<<32)|value

// ------- degrees (both branches) + W prep + scan-state reset, one kernel -----
__global__ void degree_prep_kernel(const int* __restrict__ s1, const int* __restrict__ d1, int E1,
                                   const int* __restrict__ s2, const int* __restrict__ d2, int E2,
                                   const float* __restrict__ W, int nb_edges) {
    int blk = blockIdx.x, tid = threadIdx.x;
    if (blk < nb_edges) {
        int e = blk * 256 + tid;
        if (e < E1) {
            atomicAdd(&g_deg_out[0][s1[e]], 1);
            atomicAdd(&g_deg_in[0][d1[e]], 1);
        } else if (e < E1 + E2) {
            int i = e - E1;
            atomicAdd(&g_deg_out[1][s2[i]], 1);
            atomicAdd(&g_deg_in[1][d2[i]], 1);
        }
    } else if (blk < nb_edges + 64) {
        int t = (blk - nb_edges) * 256 + tid;     // 0..16383
        int k = t >> 7, n = t & 127;
        g_WT[n * 128 + k] = __float2half_rn(W[k * 128 + n]);
    } else {
        if (tid < 2)   g_tile_counter[tid] = 0;
        if (tid < 128) g_tile_state[tid >> 6][tid & 63] = 0ull;
    }
}

// -------- decoupled-lookback scan of deg_in -> row_ptr & cursor --------------
__global__ void scan_lookback_kernel(int nnodes) {
    const int br = blockIdx.y;
    __shared__ int s_tile;
    __shared__ int ws[32];
    __shared__ int s_base;

    if (threadIdx.x == 0) s_tile = atomicAdd(&g_tile_counter[br], 1);
    __syncthreads();
    const int blk = s_tile;

    int i = blk * SCAN_TILE + threadIdx.x * 4;
    int lane = threadIdx.x & 31, w = threadIdx.x >> 5;
    int4 v = make_int4(0, 0, 0, 0);
    if (i + 3 < nnodes) v = *(const int4*)&g_deg_in[br][i];
    else {
        if (i     < nnodes) v.x = g_deg_in[br][i];
        if (i + 1 < nnodes) v.y = g_deg_in[br][i + 1];
        if (i + 2 < nnodes) v.z = g_deg_in[br][i + 2];
    }
    int s0 = v.x, s1 = s0 + v.y, s2 = s1 + v.z, s3 = s2 + v.w;
    int x = s3;
#pragma unroll
    for (int o = 1; o < 32; o <<= 1) {
        int y = __shfl_up_sync(0xffffffffu, x, o);
        if (lane >= o) x += y;
    }
    if (lane == 31) ws[w] = x;
    __syncthreads();
    if (w == 0) {
        int t = ws[lane];
#pragma unroll
        for (int o = 1; o < 32; o <<= 1) {
            int y = __shfl_up_sync(0xffffffffu, t, o);
            if (lane >= o) t += y;
        }
        ws[lane] = t;
    }
    __syncthreads();
    const int total = ws[31];

    if (threadIdx.x == 0) {
        volatile unsigned long long* st = g_tile_state[br];
        if (blk == 0) {
            st[0] = (2ull << 32) | (unsigned)total;
            s_base = 0;
        } else {
            st[blk] = (1ull << 32) | (unsigned)total;
            int base = 0;
            int p = blk - 1;
            while (p >= 0) {
                unsigned long long vv;
                do { vv = st[p]; } while ((vv >> 32) == 0ull);
                if ((vv >> 32) == 2ull) { base += (int)(unsigned)vv; break; }
                base += (int)(unsigned)vv;
                p--;
            }
            st[blk] = (2ull << 32) | (unsigned)(base + total);
            s_base = base;
        }
    }
    __syncthreads();

    int base = s_base + (w ? ws[w - 1] : 0) + (x - s3);
    int4 e = make_int4(base, base + s0, base + s1, base + s2);
    if (i + 3 < nnodes) {
        *(int4*)&g_row_ptr[br][i] = e;
        *(int4*)&g_cursor[br][i]  = e;
    } else {
        if (i     < nnodes) { g_row_ptr[br][i]     = e.x; g_cursor[br][i]     = e.x; }
        if (i + 1 < nnodes) { g_row_ptr[br][i + 1] = e.y; g_cursor[br][i + 1] = e.y; }
        if (i + 2 < nnodes) { g_row_ptr[br][i + 2] = e.z; g_cursor[br][i + 2] = e.z; }
    }
}

// ---------------- CSR fill, both branches ------------------------------------
__global__ void fill2_kernel(const int* __restrict__ s1, const int* __restrict__ d1, int E1,
                             const int* __restrict__ s2, const int* __restrict__ d2, int E2) {
    int e = blockIdx.x * blockDim.x + threadIdx.x;
    if (e < E1) {
        int pos = atomicAdd(&g_cursor[0][d1[e]], 1);
        g_csr_src[0][pos] = s1[e];
    } else if (e < E1 + E2) {
        int i = e - E1;
        int pos = atomicAdd(&g_cursor[1][d2[i]], 1);
        g_csr_src[1][pos] = s2[i];
    }
}

// ---------------- fp16 MMA / ldmatrix helpers --------------------------------
__device__ __forceinline__ void mma_f16(float4& c,
                                        unsigned a0, unsigned a1,
                                        unsigned a2, unsigned a3,
                                        unsigned b0, unsigned b1) {
    asm volatile(
        "mma.sync.aligned.m16n8k16.row.col.f32.f16.f16.f32 "
        "{%0,%1,%2,%3}, {%4,%5,%6,%7}, {%8,%9}, {%0,%1,%2,%3};\n"
        : "+f"(c.x), "+f"(c.y), "+f"(c.z), "+f"(c.w)
        : "r"(a0), "r"(a1), "r"(a2), "r"(a3), "r"(b0), "r"(b1));
}

__device__ __forceinline__ void ldsm_x4(unsigned& r0, unsigned& r1,
                                        unsigned& r2, unsigned& r3, unsigned addr) {
    asm volatile("ldmatrix.sync.aligned.m8n8.x4.shared.b16 {%0,%1,%2,%3}, [%4];"
                 : "=r"(r0), "=r"(r1), "=r"(r2), "=r"(r3) : "r"(addr));
}
__device__ __forceinline__ void ldsm_x2(unsigned& r0, unsigned& r1, unsigned addr) {
    asm volatile("ldmatrix.sync.aligned.m8n8.x2.shared.b16 {%0,%1}, [%2];"
                 : "=r"(r0), "=r"(r1) : "r"(addr));
}

// ---------------- GEMM (fp16 HMMA + ldmatrix): g_h[br] = ds * (feat @ W) -----
// block 256 (8 warps as 4x2), tile 128x128, K=128; warp tile m32 x n64 (R10)
#define AS 136  // half stride per smem row (272B, 16B-multiple -> ldmatrix ok)
__global__ void __launch_bounds__(256, 2)
gemm_fp16_kernel(const float* __restrict__ feat0, const float* __restrict__ feat1,
                 int nnodes) {
    extern __shared__ __half sm[];
    __half* sA  = sm;              // [128][AS]  feat tile (fp16), row-major
    __half* sBt = sm + 128 * AS;   // [128][AS]  W^T: [n][k]

    const int br   = blockIdx.y;
    const float* feat = br ? feat1 : feat0;
    const int tid  = threadIdx.x;
    const int row0 = blockIdx.x * 128;
    const float4* F4  = (const float4*)feat;
    const uint4*  WT4 = (const uint4*)g_WT;

#pragma unroll
    for (int i = 0; i < 8; i++) {
        int idx = tid + i * 256;          // 2048 uint4 total
        int r = idx >> 4, c = idx & 15;   // row, uint4-col (8 halves)
        float4 f0 = make_float4(0.f, 0.f, 0.f, 0.f), f1 = f0;
        if (row0 + r < nnodes) {
            f0 = F4[(size_t)(row0 + r) * 32 + 2 * c];
            f1 = F4[(size_t)(row0 + r) * 32 + 2 * c + 1];
        }
        union { __half2 h[4]; uint4 u; } p;
        p.h[0] = __floats2half2_rn(f0.x, f0.y);
        p.h[1] = __floats2half2_rn(f0.z, f0.w);
        p.h[2] = __floats2half2_rn(f1.x, f1.y);
        p.h[3] = __floats2half2_rn(f1.z, f1.w);
        *(uint4*)&sA[r * AS + c * 8] = p.u;
        *(uint4*)&sBt[r * AS + c * 8] = WT4[idx];
    }
    __syncthreads();

    const int w = tid >> 5, lane = tid & 31;
    const int wm = w & 3;
    const int warp_n = w >> 2;             // 0..1
    const int r0 = wm * 32;
    const int n0 = warp_n * 64;
    const int gid8 = lane >> 2, tig = lane & 3;

    unsigned aAddr0 = (unsigned)__cvta_generic_to_shared(
        &sA[(r0 + (lane & 15)) * AS + (lane >> 4) * 8]);
    unsigned aAddr1 = (unsigned)__cvta_generic_to_shared(
        &sA[(r0 + 16 + (lane & 15)) * AS + (lane >> 4) * 8]);
    int bl = lane & 15;
    unsigned bAddr = (unsigned)__cvta_generic_to_shared(
        &sBt[(n0 + (bl & 7)) * AS + (bl >> 3) * 8]);

    float4 c[2][8];
#pragma unroll
    for (int m = 0; m < 2; m++)
#pragma unroll
        for (int j = 0; j < 8; j++) c[m][j] = make_float4(0.f, 0.f, 0.f, 0.f);

#pragma unroll
    for (int kk = 0; kk < 8; kk++) {
        unsigned koff = kk * 32;           // 16 halves = 32 bytes
        unsigned a[2][4];
        ldsm_x4(a[0][0], a[0][1], a[0][2], a[0][3], aAddr0 + koff);
        ldsm_x4(a[1][0], a[1][1], a[1][2], a[1][3], aAddr1 + koff);
        unsigned b[8][2];
#pragma unroll
        for (int j = 0; j < 8; j++)
            ldsm_x2(b[j][0], b[j][1], bAddr + j * (8 * AS * 2) + koff);
#pragma unroll
        for (int m = 0; m < 2; m++)
#pragma unroll
            for (int j = 0; j < 8; j++)
                mma_f16(c[m][j], a[m][0], a[m][1], a[m][2], a[m][3],
                        b[j][0], b[j][1]);
    }

    unsigned* H = (unsigned*)g_h[br];
#pragma unroll
    for (int m = 0; m < 2; m++) {
        int ra = row0 + r0 + m * 16 + gid8;
        int rb = ra + 8;
        bool va = ra < nnodes, vb = rb < nnodes;
        float dsa = 0.f, dsb = 0.f;
        if (va) { int d = g_deg_out[br][ra]; dsa = rsqrtf((float)(d > 1 ? d : 1)); }
        if (vb) { int d = g_deg_out[br][rb]; dsb = rsqrtf((float)(d > 1 ? d : 1)); }
#pragma unroll
        for (int j = 0; j < 8; j++) {
            int colw = (n0 + j * 8 + 2 * tig) >> 1;  // half2 index (64 per row)
            if (va) {
                __half2 o = __floats2half2_rn(c[m][j].x * dsa, c[m][j].y * dsa);
                H[(size_t)ra * 64 + colw] = *(unsigned*)&o;
            }
            if (vb) {
                __half2 o = __floats2half2_rn(c[m][j].z * dsb, c[m][j].w * dsb);
                H[(size_t)rb * 64 + colw] = *(unsigned*)&o;
            }
        }
    }
}

// ------ gather-aggregate: half2 accumulation, fp32 flush every 8 edges -------
__global__ void gather2_kernel(const int* __restrict__ gid0,
                               const int* __restrict__ gid1,
                               const float* __restrict__ bvec, int nnodes) {
    int t = blockIdx.x * blockDim.x + threadIdx.x;
    int n2 = t >> 5;
    if (n2 >= 2 * nnodes) return;
    int br = (n2 >= nnodes) ? 1 : 0;
    int n = n2 - br * nnodes;
    int lane = t & 31;

    int beg = __ldg(&g_row_ptr[br][n]);
    int dg  = __ldg(&g_deg_in[br][n]);
    int end = beg + dg;
    const uint2* H2 = (const uint2*)g_h[br];   // 8B per lane = 4 halves
    const int* csr = g_csr_src[br];

    float4 acc = make_float4(0.f, 0.f, 0.f, 0.f);
    const __half2 hz = __floats2half2_rn(0.f, 0.f);

    int e = beg;
    for (; e + 8 <= end; e += 8) {
        int s0 = __ldg(csr + e);
        int s1 = __ldg(csr + e + 1);
        int s2 = __ldg(csr + e + 2);
        int s3 = __ldg(csr + e + 3);
        int s4 = __ldg(csr + e + 4);
        int s5 = __ldg(csr + e + 5);
        int s6 = __ldg(csr + e + 6);
        int s7 = __ldg(csr + e + 7);
        uint2 u0 = H2[(size_t)s0 * 32 + lane];
        uint2 u1 = H2[(size_t)s1 * 32 + lane];
        uint2 u2 = H2[(size_t)s2 * 32 + lane];
        uint2 u3 = H2[(size_t)s3 * 32 + lane];
        uint2 u4 = H2[(size_t)s4 * 32 + lane];
        uint2 u5 = H2[(size_t)s5 * 32 + lane];
        uint2 u6 = H2[(size_t)s6 * 32 + lane];
        uint2 u7 = H2[(size_t)s7 * 32 + lane];
        // fp16 tree-ish accumulation within the 8-edge chunk
        __half2 ha = __hadd2(*(__half2*)&u0.x, *(__half2*)&u1.x);
        __half2 hb = __hadd2(*(__half2*)&u0.y, *(__half2*)&u1.y);
        ha = __hadd2(ha, __hadd2(*(__half2*)&u2.x, *(__half2*)&u3.x));
        hb = __hadd2(hb, __hadd2(*(__half2*)&u2.y, *(__half2*)&u3.y));
        __half2 hc = __hadd2(*(__half2*)&u4.x, *(__half2*)&u5.x);
        __half2 hd = __hadd2(*(__half2*)&u4.y, *(__half2*)&u5.y);
        hc = __hadd2(hc, __hadd2(*(__half2*)&u6.x, *(__half2*)&u7.x));
        hd = __hadd2(hd, __hadd2(*(__half2*)&u6.y, *(__half2*)&u7.y));
        ha = __hadd2(ha, hc);
        hb = __hadd2(hb, hd);
        // flush chunk to fp32
        float2 f0 = __half22float2(ha);
        float2 f1 = __half22float2(hb);
        acc.x += f0.x; acc.y += f0.y; acc.z += f1.x; acc.w += f1.y;
    }
    // tail (< 8 edges): fp16 accumulate then flush once
    if (e < end) {
        __half2 ha = hz, hb = hz;
        for (; e < end; e++) {
            int s = __ldg(csr + e);
            uint2 u = H2[(size_t)s * 32 + lane];
            ha = __hadd2(ha, *(__half2*)&u.x);
            hb = __hadd2(hb, *(__half2*)&u.y);
        }
        float2 f0 = __half22float2(ha);
        float2 f1 = __half22float2(hb);
        acc.x += f0.x; acc.y += f0.y; acc.z += f1.x; acc.w += f1.y;
    }

    float din = rsqrtf((float)(dg > 1 ? dg : 1));
    float4 bb = __ldg((const float4*)bvec + lane);
    float4 v = make_float4(acc.x * din + bb.x, acc.y * din + bb.y,
                           acc.z * din + bb.z, acc.w * din + bb.w);
    float ss = v.x * v.x + v.y * v.y + v.z * v.z + v.w * v.w;
#pragma unroll
    for (int o = 16; o; o >>= 1) ss += __shfl_xor_sync(0xffffffffu, ss, o);
    float inv = 1.f / fmaxf(sqrtf(ss), 1e-12f);

    v.x = 1.f / (1.f + __expf(-v.x * inv));
    v.y = 1.f / (1.f + __expf(-v.y * inv));
    v.z = 1.f / (1.f + __expf(-v.z * inv));
    v.w = 1.f / (1.f + __expf(-v.w * inv));

    const int* gid = br ? gid1 : gid0;
    int g = __ldg(gid + n);
    atomicAdd((float4*)g_hg + (size_t)(br * NGRAPH + g) * 32 + lane, v);
    if (lane == 0) atomicAdd(&g_cnt[br * NGRAPH + g], 1);
}

// ---------------- classifier + pairwise distance (block per graph) -----------
__global__ void final_kernel(const float* __restrict__ Wc,
                             const float* __restrict__ bc,
                             float* __restrict__ out) {
    int g = blockIdx.x, tid = threadIdx.x;  // 64 threads
    __shared__ float s1[128], s2[128];
    __shared__ float part[2];

    float c1 = fmaxf((float)g_cnt[g], 1.f);
    float c2 = fmaxf((float)g_cnt[NGRAPH + g], 1.f);
    for (int i = tid; i < 128; i += 64) {
        s1[i] = g_hg[g * 128 + i] / c1;
        s2[i] = g_hg[NGRAPH * 128 + g * 128 + i] / c2;
    }
    __syncthreads();

    float l1 = bc[tid], l2 = l1;
#pragma unroll 4
    for (int k = 0; k < 128; k++) {
        float w = Wc[k * NCLASS + tid];
        l1 += s1[k] * w;
        l2 += s2[k] * w;
    }
    float dd = l1 - l2 + 1e-6f;
    float sq = dd * dd;
#pragma unroll
    for (int o = 16; o; o >>= 1) sq += __shfl_xor_sync(0xffffffffu, sq, o);
    if ((tid & 31) == 0) part[tid >> 5] = sq;
    __syncthreads();
    if (tid == 0) out[g] = sqrtf(part[0] + part[1]);
}

// ---------------- launch ------------------------------------------------------
extern "C" void kernel_launch(void* const* d_in, const int* in_sizes, int n_in,
                              void* d_out, int out_size) {
    const float* feat1 = (const float*)d_in[0];
    const float* feat2 = (const float*)d_in[1];
    const int* src1 = (const int*)d_in[2];
    const int* dst1 = (const int*)d_in[3];
    const int* gid1 = (const int*)d_in[4];
    const int* src2 = (const int*)d_in[5];
    const int* dst2 = (const int*)d_in[6];
    const int* gid2 = (const int*)d_in[7];
    const float* W  = (const float*)d_in[8];
    const float* b  = (const float*)d_in[9];
    const float* Wc = (const float*)d_in[10];
    const float* bc = (const float*)d_in[11];

    const int NN = in_sizes[0] / FEATS;
    const int E1 = in_sizes[2], E2 = in_sizes[5];
    const int nblk = (NN + SCAN_TILE - 1) / SCAN_TILE;

    void *p_deg_out, *p_deg_in, *p_hg, *p_cnt;
    cudaGetSymbolAddress(&p_deg_out, g_deg_out);
    cudaGetSymbolAddress(&p_deg_in,  g_deg_in);
    cudaGetSymbolAddress(&p_hg,      g_hg);
    cudaGetSymbolAddress(&p_cnt,     g_cnt);

    const int SMEM = 2 * 128 * AS * (int)sizeof(__half);  // 69632
    cudaFuncSetAttribute(gemm_fp16_kernel,
                         cudaFuncAttributeMaxDynamicSharedMemorySize, SMEM);

    cudaMemsetAsync(p_hg, 0, 2 * NGRAPH * FEATS * sizeof(float));
    cudaMemsetAsync(p_cnt, 0, 2 * NGRAPH * sizeof(int));
    cudaMemsetAsync(p_deg_out, 0, 2 * N_NODES_MAX * sizeof(int));
    cudaMemsetAsync(p_deg_in,  0, 2 * N_NODES_MAX * sizeof(int));

    const int nb_edges = (E1 + E2 + 255) / 256;
    degree_prep_kernel<<<nb_edges + 65, 256>>>(src1, dst1, E1, src2, dst2, E2, W, nb_edges);

    {
        dim3 grid(nblk, 2);
        scan_lookback_kernel<<<grid, 1024>>>(NN);
    }
    fill2_kernel<<<(E1 + E2 + 255) / 256, 256>>>(src1, dst1, E1, src2, dst2, E2);

    {
        dim3 grid((NN + 127) / 128, 2);
        gemm_fp16_kernel<<<grid, 256, SMEM>>>(feat1, feat2, NN);
    }
    {
        long long threads = (long long)2 * NN * 32;
        int blocks = (int)((threads + 255) / 256);
        gather2_kernel<<<blocks, 256>>>(gid1, gid2, b, NN);
    }
    final_kernel<<<NGRAPH, 64>>>(Wc, bc, (float*)d_out);
}

// round 15
// speedup vs baseline: 1.3166x; 1.0177x over previous
#include <cuda_runtime.h>
#include <cuda_fp16.h>
#include <cuda_bf16.h>

#define N_NODES_MAX 100352
#define N_EDGES_MAX 1605632
#define FEATS 128
#define NGRAPH 128
#define NCLASS 64
#define SCAN_TILE 4096

// ---------------- scratch (device globals) ----------------------------------
__device__ int    g_deg_out[2][N_NODES_MAX];
__device__ int    g_deg_in[2][N_NODES_MAX];
__device__ int    g_row_ptr[2][N_NODES_MAX];
__device__ int    g_cursor[2][N_NODES_MAX];
__device__ int    g_csr_src[2][N_EDGES_MAX];
__device__ __half g_h[2][(size_t)N_NODES_MAX * FEATS];
__device__ __half g_WT[FEATS * FEATS];           // W^T in fp16: [n][k]
__device__ float  g_hg[2 * NGRAPH * FEATS];
__device__ int    g_cnt[2 * NGRAPH];
__device__ unsigned long long g_tile_state[2][64];   // (flag<<32)|value
__device__ int    g_scan_done;

// ---------------- zero everything in one kernel ------------------------------
__global__ void zero_kernel() {
    int t = blockIdx.x * blockDim.x + threadIdx.x;
    int stride = gridDim.x * blockDim.x;
    int4 z4 = make_int4(0, 0, 0, 0);
    int4* p;
    p = (int4*)g_deg_out;
    for (int i = t; i < 2 * N_NODES_MAX / 4; i += stride) p[i] = z4;
    p = (int4*)g_deg_in;
    for (int i = t; i < 2 * N_NODES_MAX / 4; i += stride) p[i] = z4;
    p = (int4*)g_hg;
    for (int i = t; i < 2 * NGRAPH * FEATS / 4; i += stride) p[i] = z4;
    p = (int4*)g_cnt;
    for (int i = t; i < 2 * NGRAPH / 4; i += stride) p[i] = z4;
    p = (int4*)g_tile_state;
    for (int i = t; i < 2 * 64 * 8 / 16; i += stride) p[i] = z4;
    if (t == 0) g_scan_done = 0;
}

// ------- degrees (both branches) + W prep, one kernel ------------------------
__global__ void degree_prep_kernel(const int* __restrict__ s1, const int* __restrict__ d1, int E1,
                                   const int* __restrict__ s2, const int* __restrict__ d2, int E2,
                                   const float* __restrict__ W, int nb_edges) {
    int blk = blockIdx.x, tid = threadIdx.x;
    if (blk < nb_edges) {
        int e = blk * 256 + tid;
        if (e < E1) {
            atomicAdd(&g_deg_out[0][s1[e]], 1);
            atomicAdd(&g_deg_in[0][d1[e]], 1);
        } else if (e < E1 + E2) {
            int i = e - E1;
            atomicAdd(&g_deg_out[1][s2[i]], 1);
            atomicAdd(&g_deg_in[1][d2[i]], 1);
        }
    } else {
        int t = (blk - nb_edges) * 256 + tid;     // 0..16383
        int k = t >> 7, n = t & 127;
        g_WT[n * 128 + k] = __float2half_rn(W[k * 128 + n]);
    }
}

// -------- FUSED scan (lookback) + CSR fill -----------------------------------
// bids [0, 2*nscan): scan tiles (bid-derived tile id, all wave-1 resident).
// bids >= 2*nscan: fill workers — prefetch edges, spin on g_scan_done, place.
__global__ void scanfill_kernel(const int* __restrict__ s1, const int* __restrict__ d1, int E1,
                                const int* __restrict__ s2, const int* __restrict__ d2, int E2,
                                int nnodes, int nscan) {
    const int bid = blockIdx.x;
    const int tid = threadIdx.x;

    if (bid < 2 * nscan) {
        // ---------------- scan role ----------------
        const int br  = bid / nscan;
        const int blk = bid % nscan;
        __shared__ int ws[32];
        __shared__ int s_base;

        int i = blk * SCAN_TILE + tid * 4;
        int lane = tid & 31, w = tid >> 5;
        int4 v = make_int4(0, 0, 0, 0);
        if (i + 3 < nnodes) v = *(const int4*)&g_deg_in[br][i];
        else {
            if (i     < nnodes) v.x = g_deg_in[br][i];
            if (i + 1 < nnodes) v.y = g_deg_in[br][i + 1];
            if (i + 2 < nnodes) v.z = g_deg_in[br][i + 2];
        }
        int s0 = v.x, s1v = s0 + v.y, s2v = s1v + v.z, s3 = s2v + v.w;
        int x = s3;
#pragma unroll
        for (int o = 1; o < 32; o <<= 1) {
            int y = __shfl_up_sync(0xffffffffu, x, o);
            if (lane >= o) x += y;
        }
        if (lane == 31) ws[w] = x;
        __syncthreads();
        if (w == 0) {
            int t2 = ws[lane];
#pragma unroll
            for (int o = 1; o < 32; o <<= 1) {
                int y = __shfl_up_sync(0xffffffffu, t2, o);
                if (lane >= o) t2 += y;
            }
            ws[lane] = t2;
        }
        __syncthreads();
        const int total = ws[31];

        if (tid == 0) {
            volatile unsigned long long* st = g_tile_state[br];
            if (blk == 0) {
                st[0] = (2ull << 32) | (unsigned)total;
                s_base = 0;
            } else {
                st[blk] = (1ull << 32) | (unsigned)total;
                int base = 0;
                int p = blk - 1;
                while (p >= 0) {
                    unsigned long long vv;
                    do { vv = st[p]; } while ((vv >> 32) == 0ull);
                    if ((vv >> 32) == 2ull) { base += (int)(unsigned)vv; break; }
                    base += (int)(unsigned)vv;
                    p--;
                }
                st[blk] = (2ull << 32) | (unsigned)(base + total);
                s_base = base;
            }
        }
        __syncthreads();

        int base = s_base + (w ? ws[w - 1] : 0) + (x - s3);
        int4 e4 = make_int4(base, base + s0, base + s1v, base + s2v);
        if (i + 3 < nnodes) {
            *(int4*)&g_row_ptr[br][i] = e4;
            *(int4*)&g_cursor[br][i]  = e4;
        } else {
            if (i     < nnodes) { g_row_ptr[br][i]     = e4.x; g_cursor[br][i]     = e4.x; }
            if (i + 1 < nnodes) { g_row_ptr[br][i + 1] = e4.y; g_cursor[br][i + 1] = e4.y; }
            if (i + 2 < nnodes) { g_row_ptr[br][i + 2] = e4.z; g_cursor[br][i + 2] = e4.z; }
        }
        // publish completion
        __threadfence();
        __syncthreads();
        if (tid == 0) atomicAdd(&g_scan_done, 1);
    } else {
        // ---------------- fill role ----------------
        int e = (bid - 2 * nscan) * 1024 + tid;
        // prefetch edge endpoints BEFORE waiting (overlaps loads with scan)
        int s = -1, d = 0, br = 0;
        if (e < E1) { s = s1[e]; d = d1[e]; br = 0; }
        else if (e < E1 + E2) { s = s2[e - E1]; d = d2[e - E1]; br = 1; }
        // wait for all scan tiles
        if (tid == 0) {
            while (atomicAdd(&g_scan_done, 0) < 2 * nscan) { }
        }
        __syncthreads();
        __threadfence();
        if (s >= 0) {
            int pos = atomicAdd(&g_cursor[br][d], 1);
            g_csr_src[br][pos] = s;
        }
    }
}

// ---------------- fp16 MMA / ldmatrix helpers --------------------------------
__device__ __forceinline__ void mma_f16(float4& c,
                                        unsigned a0, unsigned a1,
                                        unsigned a2, unsigned a3,
                                        unsigned b0, unsigned b1) {
    asm volatile(
        "mma.sync.aligned.m16n8k16.row.col.f32.f16.f16.f32 "
        "{%0,%1,%2,%3}, {%4,%5,%6,%7}, {%8,%9}, {%0,%1,%2,%3};\n"
        : "+f"(c.x), "+f"(c.y), "+f"(c.z), "+f"(c.w)
        : "r"(a0), "r"(a1), "r"(a2), "r"(a3), "r"(b0), "r"(b1));
}

__device__ __forceinline__ void ldsm_x4(unsigned& r0, unsigned& r1,
                                        unsigned& r2, unsigned& r3, unsigned addr) {
    asm volatile("ldmatrix.sync.aligned.m8n8.x4.shared.b16 {%0,%1,%2,%3}, [%4];"
                 : "=r"(r0), "=r"(r1), "=r"(r2), "=r"(r3) : "r"(addr));
}
__device__ __forceinline__ void ldsm_x2(unsigned& r0, unsigned& r1, unsigned addr) {
    asm volatile("ldmatrix.sync.aligned.m8n8.x2.shared.b16 {%0,%1}, [%2];"
                 : "=r"(r0), "=r"(r1) : "r"(addr));
}

// ---------------- GEMM (fp16 HMMA + ldmatrix): g_h[br] = ds * (feat @ W) -----
// block 256 (8 warps as 4x2), tile 128x128, K=128; warp tile m32 x n64 (R10)
#define AS 136  // half stride per smem row (272B, 16B-multiple -> ldmatrix ok)
__global__ void __launch_bounds__(256, 2)
gemm_fp16_kernel(const float* __restrict__ feat0, const float* __restrict__ feat1,
                 int nnodes) {
    extern __shared__ __half sm[];
    __half* sA  = sm;              // [128][AS]  feat tile (fp16), row-major
    __half* sBt = sm + 128 * AS;   // [128][AS]  W^T: [n][k]

    const int br   = blockIdx.y;
    const float* feat = br ? feat1 : feat0;
    const int tid  = threadIdx.x;
    const int row0 = blockIdx.x * 128;
    const float4* F4  = (const float4*)feat;
    const uint4*  WT4 = (const uint4*)g_WT;

#pragma unroll
    for (int i = 0; i < 8; i++) {
        int idx = tid + i * 256;          // 2048 uint4 total
        int r = idx >> 4, c = idx & 15;   // row, uint4-col (8 halves)
        float4 f0 = make_float4(0.f, 0.f, 0.f, 0.f), f1 = f0;
        if (row0 + r < nnodes) {
            f0 = F4[(size_t)(row0 + r) * 32 + 2 * c];
            f1 = F4[(size_t)(row0 + r) * 32 + 2 * c + 1];
        }
        union { __half2 h[4]; uint4 u; } p;
        p.h[0] = __floats2half2_rn(f0.x, f0.y);
        p.h[1] = __floats2half2_rn(f0.z, f0.w);
        p.h[2] = __floats2half2_rn(f1.x, f1.y);
        p.h[3] = __floats2half2_rn(f1.z, f1.w);
        *(uint4*)&sA[r * AS + c * 8] = p.u;
        *(uint4*)&sBt[r * AS + c * 8] = WT4[idx];
    }
    __syncthreads();

    const int w = tid >> 5, lane = tid & 31;
    const int wm = w & 3;
    const int warp_n = w >> 2;             // 0..1
    const int r0 = wm * 32;
    const int n0 = warp_n * 64;
    const int gid8 = lane >> 2, tig = lane & 3;

    unsigned aAddr0 = (unsigned)__cvta_generic_to_shared(
        &sA[(r0 + (lane & 15)) * AS + (lane >> 4) * 8]);
    unsigned aAddr1 = (unsigned)__cvta_generic_to_shared(
        &sA[(r0 + 16 + (lane & 15)) * AS + (lane >> 4) * 8]);
    int bl = lane & 15;
    unsigned bAddr = (unsigned)__cvta_generic_to_shared(
        &sBt[(n0 + (bl & 7)) * AS + (bl >> 3) * 8]);

    float4 c[2][8];
#pragma unroll
    for (int m = 0; m < 2; m++)
#pragma unroll
        for (int j = 0; j < 8; j++) c[m][j] = make_float4(0.f, 0.f, 0.f, 0.f);

#pragma unroll
    for (int kk = 0; kk < 8; kk++) {
        unsigned koff = kk * 32;           // 16 halves = 32 bytes
        unsigned a[2][4];
        ldsm_x4(a[0][0], a[0][1], a[0][2], a[0][3], aAddr0 + koff);
        ldsm_x4(a[1][0], a[1][1], a[1][2], a[1][3], aAddr1 + koff);
        unsigned b[8][2];
#pragma unroll
        for (int j = 0; j < 8; j++)
            ldsm_x2(b[j][0], b[j][1], bAddr + j * (8 * AS * 2) + koff);
#pragma unroll
        for (int m = 0; m < 2; m++)
#pragma unroll
            for (int j = 0; j < 8; j++)
                mma_f16(c[m][j], a[m][0], a[m][1], a[m][2], a[m][3],
                        b[j][0], b[j][1]);
    }

    unsigned* H = (unsigned*)g_h[br];
#pragma unroll
    for (int m = 0; m < 2; m++) {
        int ra = row0 + r0 + m * 16 + gid8;
        int rb = ra + 8;
        bool va = ra < nnodes, vb = rb < nnodes;
        float dsa = 0.f, dsb = 0.f;
        if (va) { int d = g_deg_out[br][ra]; dsa = rsqrtf((float)(d > 1 ? d : 1)); }
        if (vb) { int d = g_deg_out[br][rb]; dsb = rsqrtf((float)(d > 1 ? d : 1)); }
#pragma unroll
        for (int j = 0; j < 8; j++) {
            int colw = (n0 + j * 8 + 2 * tig) >> 1;  // half2 index (64 per row)
            if (va) {
                __half2 o = __floats2half2_rn(c[m][j].x * dsa, c[m][j].y * dsa);
                H[(size_t)ra * 64 + colw] = *(unsigned*)&o;
            }
            if (vb) {
                __half2 o = __floats2half2_rn(c[m][j].z * dsb, c[m][j].w * dsb);
                H[(size_t)rb * 64 + colw] = *(unsigned*)&o;
            }
        }
    }
}

// ---------------- gather-aggregate + fused epilogue (warp per node) ----------
__global__ void gather2_kernel(const int* __restrict__ gid0,
                               const int* __restrict__ gid1,
                               const float* __restrict__ bvec, int nnodes) {
    int t = blockIdx.x * blockDim.x + threadIdx.x;
    int n2 = t >> 5;
    if (n2 >= 2 * nnodes) return;
    int br = (n2 >= nnodes) ? 1 : 0;
    int n = n2 - br * nnodes;
    int lane = t & 31;

    int beg = __ldg(&g_row_ptr[br][n]);
    int dg  = __ldg(&g_deg_in[br][n]);
    int end = beg + dg;
    const uint2* H2 = (const uint2*)g_h[br];   // 8B per lane = 4 halves
    const int* csr = g_csr_src[br];

    float4 acc = make_float4(0.f, 0.f, 0.f, 0.f);

#define ACCU(u) { float2 f_; \
    f_ = __half22float2(*(__half2*)&(u).x); acc.x += f_.x; acc.y += f_.y; \
    f_ = __half22float2(*(__half2*)&(u).y); acc.z += f_.x; acc.w += f_.y; }

    int e = beg;
    for (; e + 8 <= end; e += 8) {
        int s0 = __ldg(csr + e);
        int s1 = __ldg(csr + e + 1);
        int s2 = __ldg(csr + e + 2);
        int s3 = __ldg(csr + e + 3);
        int s4 = __ldg(csr + e + 4);
        int s5 = __ldg(csr + e + 5);
        int s6 = __ldg(csr + e + 6);
        int s7 = __ldg(csr + e + 7);
        uint2 u0 = H2[(size_t)s0 * 32 + lane];
        uint2 u1 = H2[(size_t)s1 * 32 + lane];
        uint2 u2 = H2[(size_t)s2 * 32 + lane];
        uint2 u3 = H2[(size_t)s3 * 32 + lane];
        uint2 u4 = H2[(size_t)s4 * 32 + lane];
        uint2 u5 = H2[(size_t)s5 * 32 + lane];
        uint2 u6 = H2[(size_t)s6 * 32 + lane];
        uint2 u7 = H2[(size_t)s7 * 32 + lane];
        ACCU(u0); ACCU(u1); ACCU(u2); ACCU(u3);
        ACCU(u4); ACCU(u5); ACCU(u6); ACCU(u7);
    }
    for (; e + 2 <= end; e += 2) {
        int s0 = __ldg(csr + e);
        int s1 = __ldg(csr + e + 1);
        uint2 u0 = H2[(size_t)s0 * 32 + lane];
        uint2 u1 = H2[(size_t)s1 * 32 + lane];
        ACCU(u0); ACCU(u1);
    }
    if (e < end) {
        int s = __ldg(csr + e);
        uint2 u = H2[(size_t)s * 32 + lane];
        ACCU(u);
    }
#undef ACCU

    float din = rsqrtf((float)(dg > 1 ? dg : 1));
    float4 bb = __ldg((const float4*)bvec + lane);
    float4 v = make_float4(acc.x * din + bb.x, acc.y * din + bb.y,
                           acc.z * din + bb.z, acc.w * din + bb.w);
    float ss = v.x * v.x + v.y * v.y + v.z * v.z + v.w * v.w;
#pragma unroll
    for (int o = 16; o; o >>= 1) ss += __shfl_xor_sync(0xffffffffu, ss, o);
    float inv = 1.f / fmaxf(sqrtf(ss), 1e-12f);

    v.x = 1.f / (1.f + __expf(-v.x * inv));
    v.y = 1.f / (1.f + __expf(-v.y * inv));
    v.z = 1.f / (1.f + __expf(-v.z * inv));
    v.w = 1.f / (1.f + __expf(-v.w * inv));

    const int* gid = br ? gid1 : gid0;
    int g = __ldg(gid + n);
    atomicAdd((float4*)g_hg + (size_t)(br * NGRAPH + g) * 32 + lane, v);
    if (lane == 0) atomicAdd(&g_cnt[br * NGRAPH + g], 1);
}

// ---------------- classifier + pairwise distance (block per graph) -----------
__global__ void final_kernel(const float* __restrict__ Wc,
                             const float* __restrict__ bc,
                             float* __restrict__ out) {
    int g = blockIdx.x, tid = threadIdx.x;  // 64 threads
    __shared__ float s1[128], s2[128];
    __shared__ float part[2];

    float c1 = fmaxf((float)g_cnt[g], 1.f);
    float c2 = fmaxf((float)g_cnt[NGRAPH + g], 1.f);
    for (int i = tid; i < 128; i += 64) {
        s1[i] = g_hg[g * 128 + i] / c1;
        s2[i] = g_hg[NGRAPH * 128 + g * 128 + i] / c2;
    }
    __syncthreads();

    float l1 = bc[tid], l2 = l1;
#pragma unroll 4
    for (int k = 0; k < 128; k++) {
        float w = Wc[k * NCLASS + tid];
        l1 += s1[k] * w;
        l2 += s2[k] * w;
    }
    float dd = l1 - l2 + 1e-6f;
    float sq = dd * dd;
#pragma unroll
    for (int o = 16; o; o >>= 1) sq += __shfl_xor_sync(0xffffffffu, sq, o);
    if ((tid & 31) == 0) part[tid >> 5] = sq;
    __syncthreads();
    if (tid == 0) out[g] = sqrtf(part[0] + part[1]);
}

// ---------------- launch ------------------------------------------------------
extern "C" void kernel_launch(void* const* d_in, const int* in_sizes, int n_in,
                              void* d_out, int out_size) {
    const float* feat1 = (const float*)d_in[0];
    const float* feat2 = (const float*)d_in[1];
    const int* src1 = (const int*)d_in[2];
    const int* dst1 = (const int*)d_in[3];
    const int* gid1 = (const int*)d_in[4];
    const int* src2 = (const int*)d_in[5];
    const int* dst2 = (const int*)d_in[6];
    const int* gid2 = (const int*)d_in[7];
    const float* W  = (const float*)d_in[8];
    const float* b  = (const float*)d_in[9];
    const float* Wc = (const float*)d_in[10];
    const float* bc = (const float*)d_in[11];

    const int NN = in_sizes[0] / FEATS;
    const int E1 = in_sizes[2], E2 = in_sizes[5];
    const int nscan = (NN + SCAN_TILE - 1) / SCAN_TILE;   // 25

    const int SMEM = 2 * 128 * AS * (int)sizeof(__half);  // 69632
    cudaFuncSetAttribute(gemm_fp16_kernel,
                         cudaFuncAttributeMaxDynamicSharedMemorySize, SMEM);

    zero_kernel<<<128, 256>>>();

    const int nb_edges = (E1 + E2 + 255) / 256;
    degree_prep_kernel<<<nb_edges + 64, 256>>>(src1, dst1, E1, src2, dst2, E2, W, nb_edges);

    {
        const int nfill = (E1 + E2 + 1023) / 1024;
        scanfill_kernel<<<2 * nscan + nfill, 1024>>>(src1, dst1, E1,
                                                     src2, dst2, E2, NN, nscan);
    }

    {
        dim3 grid((NN + 127) / 128, 2);
        gemm_fp16_kernel<<<grid, 256, SMEM>>>(feat1, feat2, NN);
    }
    {
        long long threads = (long long)2 * NN * 32;
        int blocks = (int)((threads + 255) / 256);
        gather2_kernel<<<blocks, 256>>>(gid1, gid2, b, NN);
    }
    final_kernel<<<NGRAPH, 64>>>(Wc, bc, (float*)d_out);
}